// round 11
// baseline (speedup 1.0000x reference)
#include <cuda_runtime.h>
#include <cuda_bf16.h>
#include <cstdint>

// EMD between two 8-point sets = min-cost perfect matching on the 8x8
// pairwise-distance matrix, solved with Held-Karp subset DP:
//   dp[mask] = min over j in mask of dp[mask ^ (1<<j)] + dist[popc(mask)-1][j]
//
// One warp per batch, dp in per-warp shared memory, masks processed level-by-
// level (level = popcount) with a DENSE lane assignment from a popcount-
// ordered mask table. Differences vs the earlier (slow) shared version:
//   * mask table lives in SHARED memory (divergent LDC on __constant__
//     serialized into per-line replays) and all 10 per-lane mask bytes are
//     hoisted into registers BEFORE the DP (off the critical path; ptxas
//     will not hoist loads across barriers itself).
//   * transition chains have compile-time length k (fully unrolled).
//   * dist-row reads d[(k-1)*8 + j] touch 8 distinct banks at unique
//     addresses -> shared-memory broadcast, conflict-free.
// Total ~32 transitions/lane * ~4 instr ≈ 300 warp-instructions, vs ~1500
// for the register+shuffle variant (which was issue-bound at that count).

#define WARPS_PER_BLOCK 8
#define THREADS_PER_BLOCK (WARPS_PER_BLOCK * 32)

// ---- compile-time mask table ordered by popcount --------------------------
constexpr int cpc(int m) { int c = 0; for (int i = 0; i < 8; ++i) c += (m >> i) & 1; return c; }
struct Tab { unsigned char ord[256]; };
constexpr Tab mkTab() {
    Tab t{}; int idx = 0;
    for (int k = 0; k <= 8; ++k)
        for (int m = 0; m < 256; ++m)
            if (cpc(m) == k) t.ord[idx++] = (unsigned char)m;
    return t;
}
__constant__ Tab TAB = mkTab();
// first index of masks with popcount k; counts: 1,8,28,56,70,56,28,8,1
// OFF: 0,1,9,37,93,163,219,247,255,256

// One dense DP slot: mask m (level K), chain of K unrolled transitions.
#define DO_SLOT(K, MASK, VALID)                                            \
    if (VALID) {                                                           \
        const int m_ = (MASK);                                             \
        const float* drow_ = d + ((K) - 1) * 8;                            \
        int mm_ = m_;                                                      \
        int j_ = __ffs(mm_) - 1; mm_ &= mm_ - 1;                           \
        float best_ = dp[m_ ^ (1 << j_)] + drow_[j_];                      \
        _Pragma("unroll")                                                  \
        for (int t_ = 1; t_ < (K); ++t_) {                                 \
            j_ = __ffs(mm_) - 1; mm_ &= mm_ - 1;                           \
            best_ = fminf(best_, dp[m_ ^ (1 << j_)] + drow_[j_]);          \
        }                                                                  \
        dp[m_] = best_;                                                    \
    }

__global__ void __launch_bounds__(THREADS_PER_BLOCK)
emd_assign_kernel(const float4* __restrict__ pred4,
                  const float4* __restrict__ targ4,
                  float* __restrict__ out, int B)
{
    __shared__ float  s_dist[WARPS_PER_BLOCK][64];
    __shared__ float  s_dp  [WARPS_PER_BLOCK][256];
    __shared__ float4 s_pts [WARPS_PER_BLOCK][12];
    __shared__ unsigned char s_tab[256];

    const int tid = threadIdx.x;
    // Block-wide: stage the mask table into shared (64 words).
    if (tid < 64)
        ((unsigned int*)s_tab)[tid] = ((const unsigned int*)TAB.ord)[tid];
    __syncthreads();

    const int warp = tid >> 5;
    const int lane = tid & 31;
    const int b = blockIdx.x * WARPS_PER_BLOCK + warp;
    if (b >= B) return;

    float* d  = s_dist[warp];
    float* dp = s_dp[warp];
    float* P  = (float*)s_pts[warp];   // floats 0..23  = pred [8][3]
    float* T  = P + 24;                // floats 24..47 = targ [8][3]

    // Hoist ALL per-lane masks into registers (off the DP critical path).
    const int m2  = s_tab[9   + lane];                       // lvl2, 28 masks
    const int m3a = s_tab[37  + lane];                       // lvl3, 56: slot0
    const int m3b = (lane < 24) ? s_tab[69  + lane] : 0;     //        slot1
    const int m4a = s_tab[93  + lane];                       // lvl4, 70: slot0
    const int m4b = s_tab[125 + lane];                       //        slot1
    const int m4c = (lane < 6)  ? s_tab[157 + lane] : 0;     //        slot2
    const int m5a = s_tab[163 + lane];                       // lvl5, 56: slot0
    const int m5b = (lane < 24) ? s_tab[195 + lane] : 0;     //        slot1
    const int m6  = (lane < 28) ? s_tab[219 + lane] : 0;     // lvl6, 28
    const int m7  = (lane < 8)  ? s_tab[247 + lane] : 0;     // lvl7, 8

    // Vectorized input load: 12 float4 per batch.
    if (lane < 6)       s_pts[warp][lane] = pred4[(size_t)b * 6 + lane];
    else if (lane < 12) s_pts[warp][lane] = targ4[(size_t)b * 6 + (lane - 6)];
    __syncwarp();

    // Pairwise distances: entry e = i*8+j (i = pred, j = targ); 2 per lane.
#pragma unroll
    for (int r = 0; r < 2; ++r) {
        int e = lane + r * 32;
        int i = e >> 3;
        int j = e & 7;
        float dx = P[i * 3 + 0] - T[j * 3 + 0];
        float dy = P[i * 3 + 1] - T[j * 3 + 1];
        float dz = P[i * 3 + 2] - T[j * 3 + 2];
        d[e] = sqrtf(dx * dx + dy * dy + dz * dz);
    }
    __syncwarp();

    // Level 1: dp[1<<j] = dist[0][j].
    if (lane < 8) dp[1 << lane] = d[lane];
    __syncwarp();

    DO_SLOT(2, m2, lane < 28)
    __syncwarp();
    DO_SLOT(3, m3a, true)
    DO_SLOT(3, m3b, lane < 24)
    __syncwarp();
    DO_SLOT(4, m4a, true)
    DO_SLOT(4, m4b, true)
    DO_SLOT(4, m4c, lane < 6)
    __syncwarp();
    DO_SLOT(5, m5a, true)
    DO_SLOT(5, m5b, lane < 24)
    __syncwarp();
    DO_SLOT(6, m6, lane < 28)
    __syncwarp();
    DO_SLOT(7, m7, lane < 8)
    __syncwarp();

    // Level 8 (mask 0xFF): 8 candidates in parallel + butterfly min-reduce.
    float cand = 3.4e38f;
    if (lane < 8) cand = dp[255 ^ (1 << lane)] + d[56 + lane];
    cand = fminf(cand, __shfl_xor_sync(0xffffffffu, cand, 4));
    cand = fminf(cand, __shfl_xor_sync(0xffffffffu, cand, 2));
    cand = fminf(cand, __shfl_xor_sync(0xffffffffu, cand, 1));
    if (lane == 0) out[b] = cand;
}

extern "C" void kernel_launch(void* const* d_in, const int* in_sizes, int n_in,
                              void* d_out, int out_size)
{
    const float4* pred = (const float4*)d_in[0];
    const float4* targ = (const float4*)d_in[1];
    float* out = (float*)d_out;
    int B = in_sizes[0] / 24;   // [B, 8, 3] float32
    int grid = (B + WARPS_PER_BLOCK - 1) / WARPS_PER_BLOCK;
    emd_assign_kernel<<<grid, THREADS_PER_BLOCK>>>(pred, targ, out, B);
}

// round 14
// speedup vs baseline: 1.1964x; 1.1964x over previous
#include <cuda_runtime.h>
#include <cuda_bf16.h>
#include <cstdint>

// EMD between two 8-point sets = min-cost perfect matching on the 8x8
// pairwise-distance matrix. MEET-IN-THE-MIDDLE Held-Karp:
//   f[S] = min cost of matching preds 0..popc(S)-1 to target subset S
//   g[S] = min cost of matching preds 4..3+popc(S) to target subset S
//   answer = min over |S|=4 of f[S] + g[255^S]
// Both half-DPs run only levels 1..4 (163 states each) and are INDEPENDENT,
// so their per-slot transition chains interleave (2x ILP hides LDS latency)
// and share the same mask/ffs address sequence (ALU amortized). Serial depth
// is 4 sync'd levels instead of 7. Total transitions unchanged (~1008), but
// latency exposure halves and address math is shared.
//
// One warp per batch; f/g/dist in per-warp shared; popcount-ordered mask
// table staged to shared (divergent __constant__ indexing replays); all
// per-lane mask bytes hoisted to registers before the DP.

#define WARPS_PER_BLOCK 8
#define THREADS_PER_BLOCK (WARPS_PER_BLOCK * 32)

// ---- compile-time mask table ordered by popcount --------------------------
constexpr int cpc(int m) { int c = 0; for (int i = 0; i < 8; ++i) c += (m >> i) & 1; return c; }
struct Tab { unsigned char ord[256]; };
constexpr Tab mkTab() {
    Tab t{}; int idx = 0;
    for (int k = 0; k <= 8; ++k)
        for (int m = 0; m < 256; ++m)
            if (cpc(m) == k) t.ord[idx++] = (unsigned char)m;
    return t;
}
__constant__ Tab TAB = mkTab();
// level offsets: popc k starts at {0,1,9,37,93,163,...}; counts 1,8,28,56,70

// One dense slot: mask m at level K; computes BOTH half-DP values with a
// single shared ffs/bit chain feeding two independent accumulation chains.
#define DO_SLOT2(K, MASK, VALID)                                            \
    if (VALID) {                                                            \
        const int m_ = (MASK);                                              \
        const float* drF_ = d + ((K) - 1) * 8;     /* pred row K-1   */     \
        const float* drG_ = d + ((K) + 3) * 8;     /* pred row K+3   */     \
        int mm_ = m_;                                                       \
        int j_ = __ffs(mm_) - 1; mm_ &= mm_ - 1;                            \
        int x_ = m_ ^ (1 << j_);                                            \
        float bf_ = f[x_] + drF_[j_];                                       \
        float bg_ = g[x_] + drG_[j_];                                       \
        _Pragma("unroll")                                                   \
        for (int t_ = 1; t_ < (K); ++t_) {                                  \
            j_ = __ffs(mm_) - 1; mm_ &= mm_ - 1;                            \
            x_ = m_ ^ (1 << j_);                                            \
            bf_ = fminf(bf_, f[x_] + drF_[j_]);                             \
            bg_ = fminf(bg_, g[x_] + drG_[j_]);                             \
        }                                                                   \
        f[m_] = bf_;                                                        \
        g[m_] = bg_;                                                        \
    }

__global__ void __launch_bounds__(THREADS_PER_BLOCK)
emd_assign_kernel(const float4* __restrict__ pred4,
                  const float4* __restrict__ targ4,
                  float* __restrict__ out, int B)
{
    __shared__ float  s_dist[WARPS_PER_BLOCK][64];
    __shared__ float  s_f   [WARPS_PER_BLOCK][256];
    __shared__ float  s_g   [WARPS_PER_BLOCK][256];
    __shared__ float4 s_pts [WARPS_PER_BLOCK][12];
    __shared__ unsigned char s_tab[256];

    const int tid = threadIdx.x;
    if (tid < 64)
        ((unsigned int*)s_tab)[tid] = ((const unsigned int*)TAB.ord)[tid];
    __syncthreads();

    const int warp = tid >> 5;
    const int lane = tid & 31;
    const int b = blockIdx.x * WARPS_PER_BLOCK + warp;
    if (b >= B) return;

    float* d = s_dist[warp];
    float* f = s_f[warp];
    float* g = s_g[warp];
    float* P = (float*)s_pts[warp];    // floats 0..23  = pred [8][3]
    float* T = P + 24;                 // floats 24..47 = targ [8][3]

    // Hoist all per-lane masks (levels 2..4) into registers up front.
    const int m2  = s_tab[9   + lane];                     // lvl2: 28
    const int m3a = s_tab[37  + lane];                     // lvl3: 56 slot0
    const int m3b = (lane < 24) ? s_tab[69  + lane] : 0;   //       slot1
    const int m4a = s_tab[93  + lane];                     // lvl4: 70 slot0
    const int m4b = s_tab[125 + lane];                     //       slot1
    const int m4c = (lane < 6)  ? s_tab[157 + lane] : 0;   //       slot2

    // Vectorized input load: 12 float4 per batch.
    if (lane < 6)       s_pts[warp][lane] = pred4[(size_t)b * 6 + lane];
    else if (lane < 12) s_pts[warp][lane] = targ4[(size_t)b * 6 + (lane - 6)];
    __syncwarp();

    // Pairwise distances: entry e = i*8+j (i = pred, j = targ); 2 per lane.
#pragma unroll
    for (int r = 0; r < 2; ++r) {
        int e = lane + r * 32;
        int i = e >> 3;
        int j = e & 7;
        float dx = P[i * 3 + 0] - T[j * 3 + 0];
        float dy = P[i * 3 + 1] - T[j * 3 + 1];
        float dz = P[i * 3 + 2] - T[j * 3 + 2];
        d[e] = sqrtf(dx * dx + dy * dy + dz * dz);
    }
    __syncwarp();

    // Level 1: f[1<<j] = dist(pred0, j); g[1<<j] = dist(pred4, j).
    if (lane < 8) {
        f[1 << lane] = d[lane];
        g[1 << lane] = d[32 + lane];
    }
    __syncwarp();

    DO_SLOT2(2, m2, lane < 28)
    __syncwarp();
    DO_SLOT2(3, m3a, true)
    DO_SLOT2(3, m3b, lane < 24)
    __syncwarp();
    DO_SLOT2(4, m4a, true)
    DO_SLOT2(4, m4b, true)
    DO_SLOT2(4, m4c, lane < 6)
    __syncwarp();

    // Combine: min over the 70 popc-4 subsets of f[S] + g[255^S].
    // Reuses the already-hoisted level-4 masks.
    const float INF = 3.4e38f;
    float cand = fminf(f[m4a] + g[255 ^ m4a], f[m4b] + g[255 ^ m4b]);
    if (lane < 6) cand = fminf(cand, f[m4c] + g[255 ^ m4c]);
    cand = fminf(cand, __shfl_xor_sync(0xffffffffu, cand, 16));
    cand = fminf(cand, __shfl_xor_sync(0xffffffffu, cand, 8));
    cand = fminf(cand, __shfl_xor_sync(0xffffffffu, cand, 4));
    cand = fminf(cand, __shfl_xor_sync(0xffffffffu, cand, 2));
    cand = fminf(cand, __shfl_xor_sync(0xffffffffu, cand, 1));
    if (lane == 0) out[b] = cand;
    (void)INF;
}

extern "C" void kernel_launch(void* const* d_in, const int* in_sizes, int n_in,
                              void* d_out, int out_size)
{
    const float4* pred = (const float4*)d_in[0];
    const float4* targ = (const float4*)d_in[1];
    float* out = (float*)d_out;
    int B = in_sizes[0] / 24;   // [B, 8, 3] float32
    int grid = (B + WARPS_PER_BLOCK - 1) / WARPS_PER_BLOCK;
    emd_assign_kernel<<<grid, THREADS_PER_BLOCK>>>(pred, targ, out, B);
}

// round 15
// speedup vs baseline: 1.2316x; 1.0294x over previous
#include <cuda_runtime.h>
#include <cuda_bf16.h>
#include <cstdint>

// EMD between two 8-point sets = min-cost perfect matching on the 8x8
// pairwise-distance matrix. Meet-in-the-middle Held-Karp:
//   f[S] = min matching of preds 0..popc(S)-1 to target subset S
//   g[S] = min matching of preds 4..3+popc(S) to target subset S
//   answer = min over |S|=4 of f[S] + g[255^S]
//
// TWO BATCHES PER WARP: the previous 1-batch/warp version measured 38% issue
// with every pipe <30% — a lockstep convoy of identical warps all stalling on
// the same per-level LDS chains, with occupancy hard-capped by warp count.
// Processing batches (2w, 2w+1) in one warp gives FOUR independent
// accumulation chains (fA,gA,fB,gB) that share a single ffs/mask address
// sequence: 4x latency overlap per warp, address ALU amortized 4 ways, chip
// issue floor ~ (2048 warps x ~1400 instr) / 592 SMSP ~= 4.8K cycles.

#define WARPS_PER_BLOCK 8
#define THREADS_PER_BLOCK (WARPS_PER_BLOCK * 32)

// ---- compile-time mask table ordered by popcount --------------------------
constexpr int cpc(int m) { int c = 0; for (int i = 0; i < 8; ++i) c += (m >> i) & 1; return c; }
struct Tab { unsigned char ord[256]; };
constexpr Tab mkTab() {
    Tab t{}; int idx = 0;
    for (int k = 0; k <= 8; ++k)
        for (int m = 0; m < 256; ++m)
            if (cpc(m) == k) t.ord[idx++] = (unsigned char)m;
    return t;
}
__constant__ Tab TAB = mkTab();
// level offsets: popc k starts at {0,1,9,37,93,163}; counts 1,8,28,56,70

// One dense slot: mask m at level K. One shared ffs/bit address chain feeds
// FOUR independent accumulation chains (two batches x two half-DPs).
#define DO_SLOT4(K, MASK, VALID)                                            \
    if (VALID) {                                                            \
        const int m_ = (MASK);                                              \
        const float* dAF_ = dA + ((K) - 1) * 8;                             \
        const float* dAG_ = dA + ((K) + 3) * 8;                             \
        const float* dBF_ = dB + ((K) - 1) * 8;                             \
        const float* dBG_ = dB + ((K) + 3) * 8;                             \
        int mm_ = m_;                                                       \
        int j_ = __ffs(mm_) - 1; mm_ &= mm_ - 1;                            \
        int x_ = m_ ^ (1 << j_);                                            \
        float aF_ = fA[x_] + dAF_[j_];                                      \
        float aG_ = gA[x_] + dAG_[j_];                                      \
        float bF_ = fB[x_] + dBF_[j_];                                      \
        float bG_ = gB[x_] + dBG_[j_];                                      \
        _Pragma("unroll")                                                   \
        for (int t_ = 1; t_ < (K); ++t_) {                                  \
            j_ = __ffs(mm_) - 1; mm_ &= mm_ - 1;                            \
            x_ = m_ ^ (1 << j_);                                            \
            aF_ = fminf(aF_, fA[x_] + dAF_[j_]);                            \
            aG_ = fminf(aG_, gA[x_] + dAG_[j_]);                            \
            bF_ = fminf(bF_, fB[x_] + dBF_[j_]);                            \
            bG_ = fminf(bG_, gB[x_] + dBG_[j_]);                            \
        }                                                                   \
        fA[m_] = aF_; gA[m_] = aG_; fB[m_] = bF_; gB[m_] = bG_;             \
    }

__global__ void __launch_bounds__(THREADS_PER_BLOCK)
emd_assign_kernel(const float4* __restrict__ pred4,
                  const float4* __restrict__ targ4,
                  float* __restrict__ out, int B)
{
    __shared__ float  s_dist[WARPS_PER_BLOCK][2][64];
    __shared__ float  s_f   [WARPS_PER_BLOCK][2][256];
    __shared__ float  s_g   [WARPS_PER_BLOCK][2][256];
    __shared__ float4 s_pts [WARPS_PER_BLOCK][2][12];
    __shared__ unsigned char s_tab[256];

    const int tid = threadIdx.x;
    if (tid < 64)
        ((unsigned int*)s_tab)[tid] = ((const unsigned int*)TAB.ord)[tid];
    __syncthreads();

    const int warp = tid >> 5;
    const int lane = tid & 31;
    const int b0 = (blockIdx.x * WARPS_PER_BLOCK + warp) * 2;
    if (b0 >= B) return;
    const bool haveB = (b0 + 1) < B;

    float* dA = s_dist[warp][0];
    float* dB = s_dist[warp][1];
    float* fA = s_f[warp][0];
    float* fB = s_f[warp][1];
    float* gA = s_g[warp][0];
    float* gB = s_g[warp][1];

    // Hoist all per-lane masks (levels 2..4) into registers up front.
    const int m2  = s_tab[9   + lane];                     // lvl2: 28
    const int m3a = s_tab[37  + lane];                     // lvl3: 56 slot0
    const int m3b = (lane < 24) ? s_tab[69  + lane] : 0;   //       slot1
    const int m4a = s_tab[93  + lane];                     // lvl4: 70 slot0
    const int m4b = s_tab[125 + lane];                     //       slot1
    const int m4c = (lane < 6)  ? s_tab[157 + lane] : 0;   //       slot2

    // Input load: 24 float4 per warp (12 per batch: 6 pred + 6 targ).
    if (lane < 24) {
        int bi = lane / 12;         // which batch of the pair
        int li = lane % 12;         // 0..5 pred, 6..11 targ
        int bb = b0 + bi;
        if (bb < B) {
            const float4* src = (li < 6) ? (pred4 + (size_t)bb * 6 + li)
                                         : (targ4 + (size_t)bb * 6 + (li - 6));
            s_pts[warp][bi][li] = *src;
        }
    }
    __syncwarp();

    // Pairwise distances: 128 entries (2 batches x 64); 4 per lane.
#pragma unroll
    for (int r = 0; r < 4; ++r) {
        int e  = lane + r * 32;
        int bi = e >> 6;
        int ee = e & 63;
        int i = ee >> 3;
        int j = ee & 7;
        const float* P = (const float*)s_pts[warp][bi];
        const float* T = P + 24;
        float dx = P[i * 3 + 0] - T[j * 3 + 0];
        float dy = P[i * 3 + 1] - T[j * 3 + 1];
        float dz = P[i * 3 + 2] - T[j * 3 + 2];
        s_dist[warp][bi][ee] = sqrtf(dx * dx + dy * dy + dz * dz);
    }
    __syncwarp();

    // Level 1: lanes 0..7 seed batch A, lanes 8..15 seed batch B.
    if (lane < 8) {
        fA[1 << lane] = dA[lane];
        gA[1 << lane] = dA[32 + lane];
    } else if (lane < 16) {
        int l = lane - 8;
        fB[1 << l] = dB[l];
        gB[1 << l] = dB[32 + l];
    }
    __syncwarp();

    DO_SLOT4(2, m2, lane < 28)
    __syncwarp();
    DO_SLOT4(3, m3a, true)
    DO_SLOT4(3, m3b, lane < 24)
    __syncwarp();
    DO_SLOT4(4, m4a, true)
    DO_SLOT4(4, m4b, true)
    DO_SLOT4(4, m4c, lane < 6)
    __syncwarp();

    // Combine: min over the 70 popc-4 subsets of f[S] + g[255^S], per batch.
    float cA = fminf(fA[m4a] + gA[255 ^ m4a], fA[m4b] + gA[255 ^ m4b]);
    float cB = fminf(fB[m4a] + gB[255 ^ m4a], fB[m4b] + gB[255 ^ m4b]);
    if (lane < 6) {
        cA = fminf(cA, fA[m4c] + gA[255 ^ m4c]);
        cB = fminf(cB, fB[m4c] + gB[255 ^ m4c]);
    }
#pragma unroll
    for (int s = 16; s >= 1; s >>= 1) {
        cA = fminf(cA, __shfl_xor_sync(0xffffffffu, cA, s));
        cB = fminf(cB, __shfl_xor_sync(0xffffffffu, cB, s));
    }
    if (lane == 0) {
        out[b0] = cA;
        if (haveB) out[b0 + 1] = cB;
    }
}

extern "C" void kernel_launch(void* const* d_in, const int* in_sizes, int n_in,
                              void* d_out, int out_size)
{
    const float4* pred = (const float4*)d_in[0];
    const float4* targ = (const float4*)d_in[1];
    float* out = (float*)d_out;
    int B = in_sizes[0] / 24;           // [B, 8, 3] float32
    int nPairs = (B + 1) / 2;           // one warp per 2 batches
    int grid = (nPairs + WARPS_PER_BLOCK - 1) / WARPS_PER_BLOCK;
    emd_assign_kernel<<<grid, THREADS_PER_BLOCK>>>(pred, targ, out, B);
}